// round 12
// baseline (speedup 1.0000x reference)
#include <cuda_runtime.h>
#include <cuda_bf16.h>
#include <cuda_fp16.h>
#include <cstdint>

#define D128 128
#define MAXN 50000
#define MAXE 800000
#define WSTR 68               // padded word stride (64 k-pair words + 4 pad)

// ---------------- scratch ----------------
__device__ uint32_t g_H16[MAXN * 64];   // H as half2 pairs (128 half per row)
__device__ float    g_O1[MAXN * D128];
__device__ int      g_deg[MAXN];        // real in-degree (no self loop)
__device__ float    g_dinv[MAXN];       // rsqrt(deg+1)
__device__ int      g_rowstart[MAXN];
__device__ int      g_cursor[MAXN];
__device__ int      g_csrc[MAXE];
__device__ float    g_sum[D128];
__device__ float    g_sumsq[D128];
__device__ float    g_scale[D128];
__device__ float    g_bias[D128];
__device__ uint32_t g_Wth[2 * 128 * 64];  // W^T hi bf16 k-pair packed [slot][n][p]
__device__ uint32_t g_Wtl[2 * 128 * 64];  // W^T lo

__device__ __forceinline__ uint32_t pack_bf16(float f0, float f1) {
    __nv_bfloat162 h = __floats2bfloat162_rn(f0, f1);
    return *reinterpret_cast<uint32_t*>(&h);
}

// ---------------- setup: zero deg + BN sums, split both W ----------------
__global__ void k_setup(int N, const float* __restrict__ W1, const float* __restrict__ W2) {
    int idx = blockIdx.x * blockDim.x + threadIdx.x;
    if (idx < N) g_deg[idx] = 0;
    if (idx < D128) { g_sum[idx] = 0.f; g_sumsq[idx] = 0.f; }
    if (idx < 2 * 128 * 64) {
        int slot = idx >> 13;
        int loc  = idx & 8191;
        int n = loc >> 6, p = loc & 63;
        const float* W = slot ? W2 : W1;
        float w0 = W[(2 * p) * D128 + n];
        float w1 = W[(2 * p + 1) * D128 + n];
        __nv_bfloat16 h0 = __float2bfloat16_rn(w0);
        __nv_bfloat16 h1 = __float2bfloat16_rn(w1);
        g_Wth[idx] = pack_bf16(__bfloat162float(h0), __bfloat162float(h1));
        g_Wtl[idx] = pack_bf16(w0 - __bfloat162float(h0), w1 - __bfloat162float(h1));
    }
}

__global__ void k_deg(const int* __restrict__ dst, int E) {
    int e = blockIdx.x * blockDim.x + threadIdx.x;
    if (e < E) atomicAdd(&g_deg[dst[e]], 1);
}

// ---------------- single-block scan: deg -> rowstart/cursor, dinv ----------------
__global__ __launch_bounds__(1024) void k_scanall(int N) {
    __shared__ int sh[1024];
    int t = threadIdx.x;
    int chunk = (N + 1023) / 1024;
    int start = t * chunk;
    int end = start + chunk; if (end > N) end = N;
    int sum = 0;
    for (int i = start; i < end; i++) sum += g_deg[i];
    sh[t] = sum;
    __syncthreads();
    #pragma unroll
    for (int off = 1; off < 1024; off <<= 1) {
        int add = (t >= off) ? sh[t - off] : 0;
        __syncthreads();
        sh[t] += add;
        __syncthreads();
    }
    int run = sh[t] - sum;   // exclusive base for this chunk
    for (int i = start; i < end; i++) {
        int d = g_deg[i];
        g_rowstart[i] = run;
        g_cursor[i]   = run;
        g_dinv[i]     = rsqrtf((float)(d + 1));
        run += d;
    }
}

__global__ void k_fill(const int* __restrict__ src, const int* __restrict__ dst, int E) {
    int e = blockIdx.x * blockDim.x + threadIdx.x;
    if (e >= E) return;
    int d = dst[e];
    int pos = atomicAdd(&g_cursor[d], 1);
    g_csrc[pos] = src[e];
}

// ---------------- tensor-core GEMM (writes H16 only) ----------------
#define MMA3(accp, a0,a1,a2,a3, b0,b1) \
    asm volatile("mma.sync.aligned.m16n8k16.row.col.f32.bf16.bf16.f32 " \
        "{%0,%1,%2,%3}, {%4,%5,%6,%7}, {%8,%9}, {%0,%1,%2,%3};" \
        : "+f"((accp)[0]), "+f"((accp)[1]), "+f"((accp)[2]), "+f"((accp)[3]) \
        : "r"(a0), "r"(a1), "r"(a2), "r"(a3), "r"(b0), "r"(b1))

__global__ __launch_bounds__(128) void k_gemm_tc(
    const float* __restrict__ A, int N, int wslot,
    const float* __restrict__ scl, const float* __restrict__ bia)
{
    extern __shared__ uint32_t sm[];
    uint32_t* WH = sm;                 // [128][WSTR]
    uint32_t* WL = sm + 128 * WSTR;
    uint32_t* AH = sm + 256 * WSTR;    // [64][WSTR]
    uint32_t* AL = sm + 256 * WSTR + 64 * WSTR;

    const int tid  = threadIdx.x;
    const int brow = blockIdx.x * 64;

    {
        const uint4* Wg  = (const uint4*)(g_Wth + wslot * 8192);
        const uint4* Wg2 = (const uint4*)(g_Wtl + wslot * 8192);
        #pragma unroll
        for (int i = 0; i < 16; i++) {
            int v = tid + i * 128;
            int w = v * 4;
            int r = w >> 6, c = w & 63;
            uint4 q = Wg[v];
            uint32_t* p = WH + r * WSTR + c;
            p[0] = q.x; p[1] = q.y; p[2] = q.z; p[3] = q.w;
            uint4 q2 = Wg2[v];
            uint32_t* p2 = WL + r * WSTR + c;
            p2[0] = q2.x; p2[1] = q2.y; p2[2] = q2.z; p2[3] = q2.w;
        }
    }

    #pragma unroll
    for (int i = 0; i < 16; i++) {
        int v = tid + i * 128;
        int r = v >> 5, c4 = v & 31;
        int grow = brow + r;
        float4 x = make_float4(0.f, 0.f, 0.f, 0.f);
        if (grow < N) x = ((const float4*)(A + (size_t)grow * D128))[c4];
        if (scl != nullptr) {
            int f = c4 * 4;
            x.x = fmaxf(fmaf(x.x, scl[f + 0], bia[f + 0]), 0.f);
            x.y = fmaxf(fmaf(x.y, scl[f + 1], bia[f + 1]), 0.f);
            x.z = fmaxf(fmaf(x.z, scl[f + 2], bia[f + 2]), 0.f);
            x.w = fmaxf(fmaf(x.w, scl[f + 3], bia[f + 3]), 0.f);
        }
        __nv_bfloat16 hx = __float2bfloat16_rn(x.x);
        __nv_bfloat16 hy = __float2bfloat16_rn(x.y);
        __nv_bfloat16 hz = __float2bfloat16_rn(x.z);
        __nv_bfloat16 hw = __float2bfloat16_rn(x.w);
        int base = r * WSTR + 2 * c4;
        AH[base]     = pack_bf16(__bfloat162float(hx), __bfloat162float(hy));
        AH[base + 1] = pack_bf16(__bfloat162float(hz), __bfloat162float(hw));
        AL[base]     = pack_bf16(x.x - __bfloat162float(hx), x.y - __bfloat162float(hy));
        AL[base + 1] = pack_bf16(x.z - __bfloat162float(hz), x.w - __bfloat162float(hw));
    }
    __syncthreads();

    const int lane = tid & 31, warp = tid >> 5;
    const int g = lane >> 2, t = lane & 3;
    const int wrow = warp * 16;

    float acc[16][4];
    #pragma unroll
    for (int nt = 0; nt < 16; nt++)
        #pragma unroll
        for (int j = 0; j < 4; j++) acc[nt][j] = 0.f;

    #pragma unroll
    for (int ks = 0; ks < 8; ks++) {
        const int kp = ks * 8;
        uint32_t ah0 = AH[(wrow + g)     * WSTR + kp + t];
        uint32_t ah1 = AH[(wrow + g + 8) * WSTR + kp + t];
        uint32_t ah2 = AH[(wrow + g)     * WSTR + kp + t + 4];
        uint32_t ah3 = AH[(wrow + g + 8) * WSTR + kp + t + 4];
        uint32_t al0 = AL[(wrow + g)     * WSTR + kp + t];
        uint32_t al1 = AL[(wrow + g + 8) * WSTR + kp + t];
        uint32_t al2 = AL[(wrow + g)     * WSTR + kp + t + 4];
        uint32_t al3 = AL[(wrow + g + 8) * WSTR + kp + t + 4];
        #pragma unroll
        for (int nt = 0; nt < 16; nt++) {
            int n = nt * 8 + g;
            uint32_t bh0 = WH[n * WSTR + kp + t];
            uint32_t bh1 = WH[n * WSTR + kp + t + 4];
            uint32_t bl0 = WL[n * WSTR + kp + t];
            uint32_t bl1 = WL[n * WSTR + kp + t + 4];
            MMA3(acc[nt], ah0, ah1, ah2, ah3, bh0, bh1);
            MMA3(acc[nt], ah0, ah1, ah2, ah3, bl0, bl1);
            MMA3(acc[nt], al0, al1, al2, al3, bh0, bh1);
        }
    }

    // epilogue: H16[row][col/2] = half2(acc pair)
    const int r0 = brow + wrow + g;
    const int r1 = r0 + 8;
    #pragma unroll
    for (int nt = 0; nt < 16; nt++) {
        int wcol = nt * 4 + t;            // half2 word index (col = nt*8+2t)
        if (r0 < N) {
            __half2 h = __floats2half2_rn(acc[nt][0], acc[nt][1]);
            g_H16[(size_t)r0 * 64 + wcol] = *reinterpret_cast<uint32_t*>(&h);
        }
        if (r1 < N) {
            __half2 h = __floats2half2_rn(acc[nt][2], acc[nt][3]);
            g_H16[(size_t)r1 * 64 + wcol] = *reinterpret_cast<uint32_t*>(&h);
        }
    }
}

// ---------------- CSR gather aggregation (fp16 gathers) ----------------
__device__ __forceinline__ float4 ld_h16(int row, int lane) {
    uint2 v = ((const uint2*)(g_H16 + (size_t)row * 64))[lane];
    float2 a = __half22float2(*reinterpret_cast<__half2*>(&v.x));
    float2 b = __half22float2(*reinterpret_cast<__half2*>(&v.y));
    return make_float4(a.x, a.y, b.x, b.y);
}

__global__ __launch_bounds__(256) void k_agg(
    float* __restrict__ O, const float* __restrict__ bias, int N)
{
    int node = (blockIdx.x * blockDim.x + threadIdx.x) >> 5;
    int lane = threadIdx.x & 31;
    if (node >= N) return;

    float di = g_dinv[node];
    float w  = di * di;
    float4 h = ld_h16(node, lane);
    float4 acc;
    acc.x = h.x * w; acc.y = h.y * w; acc.z = h.z * w; acc.w = h.w * w;

    const int start = g_rowstart[node];
    const int cnt   = g_deg[node];
    const int* __restrict__ cs = g_csrc + start;

    int j = 0;
    for (; j + 4 <= cnt; j += 4) {
        int s0 = cs[j], s1 = cs[j + 1], s2 = cs[j + 2], s3 = cs[j + 3];
        float n0 = g_dinv[s0] * di, n1 = g_dinv[s1] * di;
        float n2 = g_dinv[s2] * di, n3 = g_dinv[s3] * di;
        float4 v0 = ld_h16(s0, lane);
        float4 v1 = ld_h16(s1, lane);
        float4 v2 = ld_h16(s2, lane);
        float4 v3 = ld_h16(s3, lane);
        acc.x = fmaf(v0.x, n0, acc.x); acc.y = fmaf(v0.y, n0, acc.y);
        acc.z = fmaf(v0.z, n0, acc.z); acc.w = fmaf(v0.w, n0, acc.w);
        acc.x = fmaf(v1.x, n1, acc.x); acc.y = fmaf(v1.y, n1, acc.y);
        acc.z = fmaf(v1.z, n1, acc.z); acc.w = fmaf(v1.w, n1, acc.w);
        acc.x = fmaf(v2.x, n2, acc.x); acc.y = fmaf(v2.y, n2, acc.y);
        acc.z = fmaf(v2.z, n2, acc.z); acc.w = fmaf(v2.w, n2, acc.w);
        acc.x = fmaf(v3.x, n3, acc.x); acc.y = fmaf(v3.y, n3, acc.y);
        acc.z = fmaf(v3.z, n3, acc.z); acc.w = fmaf(v3.w, n3, acc.w);
    }
    for (; j < cnt; j++) {
        int s0 = cs[j];
        float n0 = g_dinv[s0] * di;
        float4 v0 = ld_h16(s0, lane);
        acc.x = fmaf(v0.x, n0, acc.x); acc.y = fmaf(v0.y, n0, acc.y);
        acc.z = fmaf(v0.z, n0, acc.z); acc.w = fmaf(v0.w, n0, acc.w);
    }

    float4 bb = ((const float4*)bias)[lane];
    acc.x += bb.x; acc.y += bb.y; acc.z += bb.z; acc.w += bb.w;
    ((float4*)(O + (size_t)node * D128))[lane] = acc;
}

// ---------------- BatchNorm ----------------
__global__ __launch_bounds__(256) void k_bnreduce(const float* __restrict__ Hx, int N) {
    int f    = threadIdx.x & 127;
    int half = threadIdx.x >> 7;
    float s = 0.f, s2 = 0.f;
    for (int row = blockIdx.x * 2 + half; row < N; row += gridDim.x * 2) {
        float v = Hx[(size_t)row * D128 + f];
        s += v;
        s2 = fmaf(v, v, s2);
    }
    __shared__ float sh[256], sh2[256];
    sh[threadIdx.x] = s; sh2[threadIdx.x] = s2;
    __syncthreads();
    if (threadIdx.x < 128) {
        atomicAdd(&g_sum[f],   sh[f] + sh[f + 128]);
        atomicAdd(&g_sumsq[f], sh2[f] + sh2[f + 128]);
    }
}

__global__ void k_bnfinal(const float* __restrict__ gamma, const float* __restrict__ beta, int N) {
    int f = threadIdx.x;
    if (f >= D128) return;
    float inv_n = 1.0f / (float)N;
    float mu  = g_sum[f] * inv_n;
    float var = g_sumsq[f] * inv_n - mu * mu;
    float rstd = rsqrtf(var + 1e-5f);
    float s = rstd * gamma[f];
    g_scale[f] = s;
    g_bias[f]  = beta[f] - mu * s;
}

// ---------------- launch ----------------
extern "C" void kernel_launch(void* const* d_in, const int* in_sizes, int n_in,
                              void* d_out, int out_size)
{
    const float* x     = (const float*)d_in[0];
    const int*   eidx  = (const int*)d_in[1];
    const float* W1    = (const float*)d_in[2];
    const float* b1    = (const float*)d_in[3];
    const float* gamma = (const float*)d_in[4];
    const float* beta  = (const float*)d_in[5];
    const float* W2    = (const float*)d_in[6];
    const float* b2    = (const float*)d_in[7];
    float*       out   = (float*)d_out;

    const int N = in_sizes[0] / D128;          // 50000
    const int E = in_sizes[1] / 2;             // 800000
    const int* src = eidx;
    const int* dst = eidx + E;

    float* O1; cudaGetSymbolAddress((void**)&O1, g_O1);
    float* scl; cudaGetSymbolAddress((void**)&scl, g_scale);
    float* bia; cudaGetSymbolAddress((void**)&bia, g_bias);

    const int GEMM_SMEM = (256 * WSTR + 128 * WSTR) * 4;   // 104448 B
    cudaFuncSetAttribute(k_gemm_tc, cudaFuncAttributeMaxDynamicSharedMemorySize, GEMM_SMEM);

    const int TPB = 256;
    int gridN  = (N + TPB - 1) / TPB;
    int gridE  = (E + TPB - 1) / TPB;
    int gridG  = (N + 63) / 64;
    int gridA  = (N * 32 + TPB - 1) / TPB;     // warp per node

    // graph structure (per call, deterministic)
    k_setup<<<gridN, TPB>>>(N, W1, W2);
    k_deg<<<gridE, TPB>>>(dst, E);
    k_scanall<<<1, 1024>>>(N);
    k_fill<<<gridE, TPB>>>(src, dst, E);

    // layer 1
    k_gemm_tc<<<gridG, 128, GEMM_SMEM>>>(x, N, 0, nullptr, nullptr);
    k_agg<<<gridA, TPB>>>(O1, b1, N);

    // batchnorm stats -> scale/bias
    k_bnreduce<<<256, TPB>>>(O1, N);
    k_bnfinal<<<1, 128>>>(gamma, beta, N);

    // layer 2 (BN+ReLU fused into A load)
    k_gemm_tc<<<gridG, 128, GEMM_SMEM>>>(O1, N, 1, scl, bia);
    k_agg<<<gridA, TPB>>>(out, b2, N);
}

// round 14
// speedup vs baseline: 1.5401x; 1.5401x over previous
#include <cuda_runtime.h>
#include <cuda_bf16.h>
#include <cuda_fp16.h>
#include <cstdint>

#define D128 128
#define MAXN 50000
#define MAXE 800000
#define WSTR 68               // padded word stride (64 k-pair words + 4 pad)
#define SCAN_TPB 256

// ---------------- scratch ----------------
__device__ uint32_t g_H16[MAXN * 64];   // H rows as 64 half2 words (128 half)
__device__ float    g_O1[MAXN * D128];
__device__ int      g_deg[MAXN];        // real in-degree (no self loop)
__device__ float    g_dinv[MAXN];       // rsqrt(deg+1)
__device__ int      g_rowstart[MAXN];
__device__ int      g_cursor[MAXN];
__device__ int      g_csrc[MAXE];
__device__ int      g_blocksum[SCAN_TPB];
__device__ float    g_sum[D128];
__device__ float    g_sumsq[D128];
__device__ float    g_scale[D128];
__device__ float    g_bias[D128];
__device__ uint32_t g_Wth[2 * 128 * 64];  // W^T hi bf16 k-pair packed [slot][n][p]
__device__ uint32_t g_Wtl[2 * 128 * 64];  // W^T lo

__device__ __forceinline__ uint32_t pack_bf16(float f0, float f1) {
    __nv_bfloat162 h = __floats2bfloat162_rn(f0, f1);
    return *reinterpret_cast<uint32_t*>(&h);
}

// ---------------- setup: zero deg + BN sums, split both W ----------------
__global__ void k_setup(int N, const float* __restrict__ W1, const float* __restrict__ W2) {
    int idx = blockIdx.x * blockDim.x + threadIdx.x;
    if (idx < N) g_deg[idx] = 0;
    if (idx < D128) { g_sum[idx] = 0.f; g_sumsq[idx] = 0.f; }
    if (idx < 2 * 128 * 64) {
        int slot = idx >> 13;
        int loc  = idx & 8191;
        int n = loc >> 6, p = loc & 63;
        const float* W = slot ? W2 : W1;
        float w0 = W[(2 * p) * D128 + n];
        float w1 = W[(2 * p + 1) * D128 + n];
        __nv_bfloat16 h0 = __float2bfloat16_rn(w0);
        __nv_bfloat16 h1 = __float2bfloat16_rn(w1);
        g_Wth[idx] = pack_bf16(__bfloat162float(h0), __bfloat162float(h1));
        g_Wtl[idx] = pack_bf16(w0 - __bfloat162float(h0), w1 - __bfloat162float(h1));
    }
}

// ---------------- degree (4 edges/thread, int4) ----------------
__global__ void k_deg(const int* __restrict__ dst, int E) {
    int e4 = (blockIdx.x * blockDim.x + threadIdx.x) * 4;
    if (e4 + 3 < E) {
        int4 d = *(const int4*)(dst + e4);
        atomicAdd(&g_deg[d.x], 1);
        atomicAdd(&g_deg[d.y], 1);
        atomicAdd(&g_deg[d.z], 1);
        atomicAdd(&g_deg[d.w], 1);
    } else {
        for (int e = e4; e < E; e++) atomicAdd(&g_deg[dst[e]], 1);
    }
}

// ---------------- scan of deg -> rowstart, plus dinv (R8-proven 3-kernel) ----------------
__global__ void k_scan1(int N) {
    __shared__ int sh[SCAN_TPB];
    int t = threadIdx.x;
    int i = blockIdx.x * SCAN_TPB + t;
    int v = (i < N) ? g_deg[i] : 0;
    if (i < N) g_dinv[i] = rsqrtf((float)(v + 1));
    sh[t] = v;
    __syncthreads();
    #pragma unroll
    for (int off = 1; off < SCAN_TPB; off <<= 1) {
        int add = (t >= off) ? sh[t - off] : 0;
        __syncthreads();
        sh[t] += add;
        __syncthreads();
    }
    if (i < N) g_rowstart[i] = sh[t] - v;
    if (t == SCAN_TPB - 1) g_blocksum[blockIdx.x] = sh[t];
}
__global__ void k_scan2(int nblocks) {
    __shared__ int sh[SCAN_TPB];
    int t = threadIdx.x;
    int v = (t < nblocks) ? g_blocksum[t] : 0;
    sh[t] = v;
    __syncthreads();
    #pragma unroll
    for (int off = 1; off < SCAN_TPB; off <<= 1) {
        int add = (t >= off) ? sh[t - off] : 0;
        __syncthreads();
        sh[t] += add;
        __syncthreads();
    }
    g_blocksum[t] = sh[t] - v;
}
__global__ void k_scan3(int N) {
    int i = blockIdx.x * blockDim.x + threadIdx.x;
    if (i >= N) return;
    int rs = g_rowstart[i] + g_blocksum[i / SCAN_TPB];
    g_rowstart[i] = rs;
    g_cursor[i]   = rs;
}

// ---------------- CSR fill (4 edges/thread, int4) ----------------
__global__ void k_fill(const int* __restrict__ src, const int* __restrict__ dst, int E) {
    int e4 = (blockIdx.x * blockDim.x + threadIdx.x) * 4;
    if (e4 + 3 < E) {
        int4 d = *(const int4*)(dst + e4);
        int4 s = *(const int4*)(src + e4);
        g_csrc[atomicAdd(&g_cursor[d.x], 1)] = s.x;
        g_csrc[atomicAdd(&g_cursor[d.y], 1)] = s.y;
        g_csrc[atomicAdd(&g_cursor[d.z], 1)] = s.z;
        g_csrc[atomicAdd(&g_cursor[d.w], 1)] = s.w;
    } else {
        for (int e = e4; e < E; e++)
            g_csrc[atomicAdd(&g_cursor[dst[e]], 1)] = src[e];
    }
}

// ---------------- tensor-core GEMM (writes H16 only) ----------------
#define MMA3(accp, a0,a1,a2,a3, b0,b1) \
    asm volatile("mma.sync.aligned.m16n8k16.row.col.f32.bf16.bf16.f32 " \
        "{%0,%1,%2,%3}, {%4,%5,%6,%7}, {%8,%9}, {%0,%1,%2,%3};" \
        : "+f"((accp)[0]), "+f"((accp)[1]), "+f"((accp)[2]), "+f"((accp)[3]) \
        : "r"(a0), "r"(a1), "r"(a2), "r"(a3), "r"(b0), "r"(b1))

__global__ __launch_bounds__(128) void k_gemm_tc(
    const float* __restrict__ A, int N, int wslot,
    const float* __restrict__ scl, const float* __restrict__ bia)
{
    extern __shared__ uint32_t sm[];
    uint32_t* WH = sm;                 // [128][WSTR]
    uint32_t* WL = sm + 128 * WSTR;
    uint32_t* AH = sm + 256 * WSTR;    // [64][WSTR]
    uint32_t* AL = sm + 256 * WSTR + 64 * WSTR;

    const int tid  = threadIdx.x;
    const int brow = blockIdx.x * 64;

    {
        const uint4* Wg  = (const uint4*)(g_Wth + wslot * 8192);
        const uint4* Wg2 = (const uint4*)(g_Wtl + wslot * 8192);
        #pragma unroll
        for (int i = 0; i < 16; i++) {
            int v = tid + i * 128;
            int w = v * 4;
            int r = w >> 6, c = w & 63;
            uint4 q = Wg[v];
            uint32_t* p = WH + r * WSTR + c;
            p[0] = q.x; p[1] = q.y; p[2] = q.z; p[3] = q.w;
            uint4 q2 = Wg2[v];
            uint32_t* p2 = WL + r * WSTR + c;
            p2[0] = q2.x; p2[1] = q2.y; p2[2] = q2.z; p2[3] = q2.w;
        }
    }

    #pragma unroll
    for (int i = 0; i < 16; i++) {
        int v = tid + i * 128;
        int r = v >> 5, c4 = v & 31;
        int grow = brow + r;
        float4 x = make_float4(0.f, 0.f, 0.f, 0.f);
        if (grow < N) x = ((const float4*)(A + (size_t)grow * D128))[c4];
        if (scl != nullptr) {
            int f = c4 * 4;
            x.x = fmaxf(fmaf(x.x, scl[f + 0], bia[f + 0]), 0.f);
            x.y = fmaxf(fmaf(x.y, scl[f + 1], bia[f + 1]), 0.f);
            x.z = fmaxf(fmaf(x.z, scl[f + 2], bia[f + 2]), 0.f);
            x.w = fmaxf(fmaf(x.w, scl[f + 3], bia[f + 3]), 0.f);
        }
        __nv_bfloat16 hx = __float2bfloat16_rn(x.x);
        __nv_bfloat16 hy = __float2bfloat16_rn(x.y);
        __nv_bfloat16 hz = __float2bfloat16_rn(x.z);
        __nv_bfloat16 hw = __float2bfloat16_rn(x.w);
        int base = r * WSTR + 2 * c4;
        AH[base]     = pack_bf16(__bfloat162float(hx), __bfloat162float(hy));
        AH[base + 1] = pack_bf16(__bfloat162float(hz), __bfloat162float(hw));
        AL[base]     = pack_bf16(x.x - __bfloat162float(hx), x.y - __bfloat162float(hy));
        AL[base + 1] = pack_bf16(x.z - __bfloat162float(hz), x.w - __bfloat162float(hw));
    }
    __syncthreads();

    const int lane = tid & 31, warp = tid >> 5;
    const int g = lane >> 2, t = lane & 3;
    const int wrow = warp * 16;

    float acc[16][4];
    #pragma unroll
    for (int nt = 0; nt < 16; nt++)
        #pragma unroll
        for (int j = 0; j < 4; j++) acc[nt][j] = 0.f;

    #pragma unroll
    for (int ks = 0; ks < 8; ks++) {
        const int kp = ks * 8;
        uint32_t ah0 = AH[(wrow + g)     * WSTR + kp + t];
        uint32_t ah1 = AH[(wrow + g + 8) * WSTR + kp + t];
        uint32_t ah2 = AH[(wrow + g)     * WSTR + kp + t + 4];
        uint32_t ah3 = AH[(wrow + g + 8) * WSTR + kp + t + 4];
        uint32_t al0 = AL[(wrow + g)     * WSTR + kp + t];
        uint32_t al1 = AL[(wrow + g + 8) * WSTR + kp + t];
        uint32_t al2 = AL[(wrow + g)     * WSTR + kp + t + 4];
        uint32_t al3 = AL[(wrow + g + 8) * WSTR + kp + t + 4];
        #pragma unroll
        for (int nt = 0; nt < 16; nt++) {
            int n = nt * 8 + g;
            uint32_t bh0 = WH[n * WSTR + kp + t];
            uint32_t bh1 = WH[n * WSTR + kp + t + 4];
            uint32_t bl0 = WL[n * WSTR + kp + t];
            uint32_t bl1 = WL[n * WSTR + kp + t + 4];
            MMA3(acc[nt], ah0, ah1, ah2, ah3, bh0, bh1);
            MMA3(acc[nt], ah0, ah1, ah2, ah3, bl0, bl1);
            MMA3(acc[nt], al0, al1, al2, al3, bh0, bh1);
        }
    }

    // epilogue: H16[row] packed half2
    const int r0 = brow + wrow + g;
    const int r1 = r0 + 8;
    #pragma unroll
    for (int nt = 0; nt < 16; nt++) {
        int wcol = nt * 4 + t;            // half2 word index (cols nt*8+2t, +1)
        if (r0 < N) {
            __half2 h = __floats2half2_rn(acc[nt][0], acc[nt][1]);
            g_H16[(size_t)r0 * 64 + wcol] = *reinterpret_cast<uint32_t*>(&h);
        }
        if (r1 < N) {
            __half2 h = __floats2half2_rn(acc[nt][2], acc[nt][3]);
            g_H16[(size_t)r1 * 64 + wcol] = *reinterpret_cast<uint32_t*>(&h);
        }
    }
}

// ---------------- CSR gather aggregation (fp16 gathers, R8 structure) ----------------
__device__ __forceinline__ float4 ld_h16(int row, int lane) {
    uint2 v = ((const uint2*)(g_H16 + (size_t)row * 64))[lane];
    float2 a = __half22float2(*reinterpret_cast<__half2*>(&v.x));
    float2 b = __half22float2(*reinterpret_cast<__half2*>(&v.y));
    return make_float4(a.x, a.y, b.x, b.y);
}

__global__ __launch_bounds__(256) void k_agg(
    float* __restrict__ O, const float* __restrict__ bias, int N)
{
    int node = (blockIdx.x * blockDim.x + threadIdx.x) >> 5;
    int lane = threadIdx.x & 31;
    if (node >= N) return;

    float di = g_dinv[node];
    float w  = di * di;
    float4 h = ld_h16(node, lane);
    float4 acc;
    acc.x = h.x * w; acc.y = h.y * w; acc.z = h.z * w; acc.w = h.w * w;

    const int start = g_rowstart[node];
    const int cnt   = g_deg[node];
    const int* __restrict__ cs = g_csrc + start;

    int j = 0;
    for (; j + 2 <= cnt; j += 2) {
        int s0 = cs[j];
        int s1 = cs[j + 1];
        float n0 = g_dinv[s0] * di;
        float n1 = g_dinv[s1] * di;
        float4 v0 = ld_h16(s0, lane);
        float4 v1 = ld_h16(s1, lane);
        acc.x = fmaf(v0.x, n0, acc.x); acc.y = fmaf(v0.y, n0, acc.y);
        acc.z = fmaf(v0.z, n0, acc.z); acc.w = fmaf(v0.w, n0, acc.w);
        acc.x = fmaf(v1.x, n1, acc.x); acc.y = fmaf(v1.y, n1, acc.y);
        acc.z = fmaf(v1.z, n1, acc.z); acc.w = fmaf(v1.w, n1, acc.w);
    }
    if (j < cnt) {
        int s0 = cs[j];
        float n0 = g_dinv[s0] * di;
        float4 v0 = ld_h16(s0, lane);
        acc.x = fmaf(v0.x, n0, acc.x); acc.y = fmaf(v0.y, n0, acc.y);
        acc.z = fmaf(v0.z, n0, acc.z); acc.w = fmaf(v0.w, n0, acc.w);
    }

    float4 bb = ((const float4*)bias)[lane];
    acc.x += bb.x; acc.y += bb.y; acc.z += bb.z; acc.w += bb.w;
    ((float4*)(O + (size_t)node * D128))[lane] = acc;
}

// ---------------- BatchNorm (R8 standalone) ----------------
__global__ __launch_bounds__(256) void k_bnreduce(const float* __restrict__ Hx, int N) {
    int f    = threadIdx.x & 127;
    int half = threadIdx.x >> 7;
    float s = 0.f, s2 = 0.f;
    for (int row = blockIdx.x * 2 + half; row < N; row += gridDim.x * 2) {
        float v = Hx[(size_t)row * D128 + f];
        s += v;
        s2 = fmaf(v, v, s2);
    }
    __shared__ float sh[256], sh2[256];
    sh[threadIdx.x] = s; sh2[threadIdx.x] = s2;
    __syncthreads();
    if (threadIdx.x < 128) {
        atomicAdd(&g_sum[f],   sh[f] + sh[f + 128]);
        atomicAdd(&g_sumsq[f], sh2[f] + sh2[f + 128]);
    }
}
__global__ void k_bnfinal(const float* __restrict__ gamma, const float* __restrict__ beta, int N) {
    int f = threadIdx.x;
    if (f >= D128) return;
    float inv_n = 1.0f / (float)N;
    float mu  = g_sum[f] * inv_n;
    float var = g_sumsq[f] * inv_n - mu * mu;
    float rstd = rsqrtf(var + 1e-5f);
    float s = rstd * gamma[f];
    g_scale[f] = s;
    g_bias[f]  = beta[f] - mu * s;
}

// ---------------- launch ----------------
extern "C" void kernel_launch(void* const* d_in, const int* in_sizes, int n_in,
                              void* d_out, int out_size)
{
    const float* x     = (const float*)d_in[0];
    const int*   eidx  = (const int*)d_in[1];
    const float* W1    = (const float*)d_in[2];
    const float* b1    = (const float*)d_in[3];
    const float* gamma = (const float*)d_in[4];
    const float* beta  = (const float*)d_in[5];
    const float* W2    = (const float*)d_in[6];
    const float* b2    = (const float*)d_in[7];
    float*       out   = (float*)d_out;

    const int N = in_sizes[0] / D128;          // 50000
    const int E = in_sizes[1] / 2;             // 800000
    const int* src = eidx;
    const int* dst = eidx + E;

    float* O1; cudaGetSymbolAddress((void**)&O1, g_O1);
    float* scl; cudaGetSymbolAddress((void**)&scl, g_scale);
    float* bia; cudaGetSymbolAddress((void**)&bia, g_bias);

    const int GEMM_SMEM = (256 * WSTR + 128 * WSTR) * 4;   // 104448 B
    cudaFuncSetAttribute(k_gemm_tc, cudaFuncAttributeMaxDynamicSharedMemorySize, GEMM_SMEM);

    const int TPB = 256;
    int gridN  = (N + TPB - 1) / TPB;
    int gridE4 = ((E + 3) / 4 + TPB - 1) / TPB;
    int gridG  = (N + 63) / 64;
    int gridA  = (N * 32 + TPB - 1) / TPB;     // warp per node
    int nscan  = (N + SCAN_TPB - 1) / SCAN_TPB;

    // graph structure (per call, deterministic)
    k_setup<<<gridN, TPB>>>(N, W1, W2);
    k_deg<<<gridE4, TPB>>>(dst, E);
    k_scan1<<<nscan, SCAN_TPB>>>(N);
    k_scan2<<<1, SCAN_TPB>>>(nscan);
    k_scan3<<<gridN, TPB>>>(N);
    k_fill<<<gridE4, TPB>>>(src, dst, E);

    // layer 1
    k_gemm_tc<<<gridG, 128, GEMM_SMEM>>>(x, N, 0, nullptr, nullptr);
    k_agg<<<gridA, TPB>>>(O1, b1, N);

    // batchnorm stats -> scale/bias
    k_bnreduce<<<256, TPB>>>(O1, N);
    k_bnfinal<<<1, 128>>>(gamma, beta, N);

    // layer 2 (BN+ReLU fused into A load)
    k_gemm_tc<<<gridG, 128, GEMM_SMEM>>>(O1, N, 1, scl, bia);
    k_agg<<<gridA, TPB>>>(out, b2, N);
}

// round 16
// speedup vs baseline: 1.5948x; 1.0355x over previous
#include <cuda_runtime.h>
#include <cuda_bf16.h>
#include <cuda_fp16.h>
#include <cstdint>

#define D128 128
#define MAXN 50000
#define MAXE 800000
#define WSTR 68               // padded word stride (64 k-pair words + 4 pad)
#define SCAN_TPB 256

// ---------------- scratch ----------------
__device__ uint32_t g_H16[MAXN * 64];   // H rows as 64 half2 words (128 half)
__device__ float    g_O1[MAXN * D128];
__device__ int      g_deg[MAXN];        // real in-degree (no self loop)
__device__ float    g_dinv[MAXN];       // rsqrt(deg+1)
__device__ int      g_rowstart[MAXN];
__device__ int      g_cursor[MAXN];
__device__ int      g_csrc[MAXE];
__device__ int      g_blocksum[SCAN_TPB];
__device__ float    g_sum[D128];
__device__ float    g_sumsq[D128];
__device__ uint32_t g_Wth[2 * 128 * 64];  // W^T hi bf16 k-pair packed [slot][n][p]
__device__ uint32_t g_Wtl[2 * 128 * 64];  // W^T lo

__device__ __forceinline__ uint32_t pack_bf16(float f0, float f1) {
    __nv_bfloat162 h = __floats2bfloat162_rn(f0, f1);
    return *reinterpret_cast<uint32_t*>(&h);
}

// ---------------- setup: zero deg + BN sums, split both W ----------------
__global__ void k_setup(int N, const float* __restrict__ W1, const float* __restrict__ W2) {
    int idx = blockIdx.x * blockDim.x + threadIdx.x;
    if (idx < N) g_deg[idx] = 0;
    if (idx < D128) { g_sum[idx] = 0.f; g_sumsq[idx] = 0.f; }
    if (idx < 2 * 128 * 64) {
        int slot = idx >> 13;
        int loc  = idx & 8191;
        int n = loc >> 6, p = loc & 63;
        const float* W = slot ? W2 : W1;
        float w0 = W[(2 * p) * D128 + n];
        float w1 = W[(2 * p + 1) * D128 + n];
        __nv_bfloat16 h0 = __float2bfloat16_rn(w0);
        __nv_bfloat16 h1 = __float2bfloat16_rn(w1);
        g_Wth[idx] = pack_bf16(__bfloat162float(h0), __bfloat162float(h1));
        g_Wtl[idx] = pack_bf16(w0 - __bfloat162float(h0), w1 - __bfloat162float(h1));
    }
}

// ---------------- degree (4 edges/thread, int4) ----------------
__global__ void k_deg(const int* __restrict__ dst, int E) {
    int e4 = (blockIdx.x * blockDim.x + threadIdx.x) * 4;
    if (e4 + 3 < E) {
        int4 d = *(const int4*)(dst + e4);
        atomicAdd(&g_deg[d.x], 1);
        atomicAdd(&g_deg[d.y], 1);
        atomicAdd(&g_deg[d.z], 1);
        atomicAdd(&g_deg[d.w], 1);
    } else {
        for (int e = e4; e < E; e++) atomicAdd(&g_deg[dst[e]], 1);
    }
}

// ---------------- scan of deg (2 kernels; scan3 self-computes block offset) ----------------
__global__ void k_scan1(int N) {
    __shared__ int sh[SCAN_TPB];
    int t = threadIdx.x;
    int i = blockIdx.x * SCAN_TPB + t;
    int v = (i < N) ? g_deg[i] : 0;
    if (i < N) g_dinv[i] = rsqrtf((float)(v + 1));
    sh[t] = v;
    __syncthreads();
    #pragma unroll
    for (int off = 1; off < SCAN_TPB; off <<= 1) {
        int add = (t >= off) ? sh[t - off] : 0;
        __syncthreads();
        sh[t] += add;
        __syncthreads();
    }
    if (i < N) g_rowstart[i] = sh[t] - v;
    if (t == SCAN_TPB - 1) g_blocksum[blockIdx.x] = sh[t];
}
__global__ void k_scan3(int N) {
    __shared__ int sh[SCAN_TPB];
    int t = threadIdx.x;
    int partial = 0;
    for (int i = t; i < (int)blockIdx.x; i += SCAN_TPB) partial += g_blocksum[i];
    sh[t] = partial;
    __syncthreads();
    #pragma unroll
    for (int off = SCAN_TPB / 2; off > 0; off >>= 1) {
        if (t < off) sh[t] += sh[t + off];
        __syncthreads();
    }
    int base = sh[0];
    int i = blockIdx.x * SCAN_TPB + t;
    if (i < N) {
        int rs = g_rowstart[i] + base;
        g_rowstart[i] = rs;
        g_cursor[i]   = rs;
    }
}

// ---------------- CSR fill (4 edges/thread, int4) ----------------
__global__ void k_fill(const int* __restrict__ src, const int* __restrict__ dst, int E) {
    int e4 = (blockIdx.x * blockDim.x + threadIdx.x) * 4;
    if (e4 + 3 < E) {
        int4 d = *(const int4*)(dst + e4);
        int4 s = *(const int4*)(src + e4);
        g_csrc[atomicAdd(&g_cursor[d.x], 1)] = s.x;
        g_csrc[atomicAdd(&g_cursor[d.y], 1)] = s.y;
        g_csrc[atomicAdd(&g_cursor[d.z], 1)] = s.z;
        g_csrc[atomicAdd(&g_cursor[d.w], 1)] = s.w;
    } else {
        for (int e = e4; e < E; e++)
            g_csrc[atomicAdd(&g_cursor[dst[e]], 1)] = src[e];
    }
}

// ---------------- tensor-core GEMM (writes H16 only; optional in-kernel BN coef) ----------------
#define MMA3(accp, a0,a1,a2,a3, b0,b1) \
    asm volatile("mma.sync.aligned.m16n8k16.row.col.f32.bf16.bf16.f32 " \
        "{%0,%1,%2,%3}, {%4,%5,%6,%7}, {%8,%9}, {%0,%1,%2,%3};" \
        : "+f"((accp)[0]), "+f"((accp)[1]), "+f"((accp)[2]), "+f"((accp)[3]) \
        : "r"(a0), "r"(a1), "r"(a2), "r"(a3), "r"(b0), "r"(b1))

__global__ __launch_bounds__(128) void k_gemm_tc(
    const float* __restrict__ A, int N, int wslot,
    const float* __restrict__ gamma, const float* __restrict__ beta)
{
    extern __shared__ uint32_t sm[];
    uint32_t* WH = sm;                 // [128][WSTR]
    uint32_t* WL = sm + 128 * WSTR;
    uint32_t* AH = sm + 256 * WSTR;    // [64][WSTR]
    uint32_t* AL = sm + 256 * WSTR + 64 * WSTR;
    float*    BNs = (float*)(sm + 384 * WSTR);   // [128]
    float*    BNb = BNs + 128;                   // [128]

    const int tid  = threadIdx.x;
    const int brow = blockIdx.x * 64;
    const bool do_bn = (gamma != nullptr);

    // ---- BN coefficients (layer 2): every block derives them from g_sum/g_sumsq ----
    if (do_bn) {
        float inv_n = 1.0f / (float)N;
        float mu  = g_sum[tid] * inv_n;
        float var = g_sumsq[tid] * inv_n - mu * mu;
        float rstd = rsqrtf(var + 1e-5f);
        float s = rstd * gamma[tid];
        BNs[tid] = s;
        BNb[tid] = beta[tid] - mu * s;
    }

    // ---- load W tiles ----
    {
        const uint4* Wg  = (const uint4*)(g_Wth + wslot * 8192);
        const uint4* Wg2 = (const uint4*)(g_Wtl + wslot * 8192);
        #pragma unroll
        for (int i = 0; i < 16; i++) {
            int v = tid + i * 128;
            int w = v * 4;
            int r = w >> 6, c = w & 63;
            uint4 q = Wg[v];
            uint32_t* p = WH + r * WSTR + c;
            p[0] = q.x; p[1] = q.y; p[2] = q.z; p[3] = q.w;
            uint4 q2 = Wg2[v];
            uint32_t* p2 = WL + r * WSTR + c;
            p2[0] = q2.x; p2[1] = q2.y; p2[2] = q2.z; p2[3] = q2.w;
        }
    }
    __syncthreads();   // BN coefs (and W) visible before A-load uses them

    // ---- load A tile, optional BN+ReLU, split to bf16 hi/lo ----
    #pragma unroll
    for (int i = 0; i < 16; i++) {
        int v = tid + i * 128;
        int r = v >> 5, c4 = v & 31;
        int grow = brow + r;
        float4 x = make_float4(0.f, 0.f, 0.f, 0.f);
        if (grow < N) x = ((const float4*)(A + (size_t)grow * D128))[c4];
        if (do_bn) {
            int f = c4 * 4;
            x.x = fmaxf(fmaf(x.x, BNs[f + 0], BNb[f + 0]), 0.f);
            x.y = fmaxf(fmaf(x.y, BNs[f + 1], BNb[f + 1]), 0.f);
            x.z = fmaxf(fmaf(x.z, BNs[f + 2], BNb[f + 2]), 0.f);
            x.w = fmaxf(fmaf(x.w, BNs[f + 3], BNb[f + 3]), 0.f);
        }
        __nv_bfloat16 hx = __float2bfloat16_rn(x.x);
        __nv_bfloat16 hy = __float2bfloat16_rn(x.y);
        __nv_bfloat16 hz = __float2bfloat16_rn(x.z);
        __nv_bfloat16 hw = __float2bfloat16_rn(x.w);
        int base = r * WSTR + 2 * c4;
        AH[base]     = pack_bf16(__bfloat162float(hx), __bfloat162float(hy));
        AH[base + 1] = pack_bf16(__bfloat162float(hz), __bfloat162float(hw));
        AL[base]     = pack_bf16(x.x - __bfloat162float(hx), x.y - __bfloat162float(hy));
        AL[base + 1] = pack_bf16(x.z - __bfloat162float(hz), x.w - __bfloat162float(hw));
    }
    __syncthreads();

    const int lane = tid & 31, warp = tid >> 5;
    const int g = lane >> 2, t = lane & 3;
    const int wrow = warp * 16;

    float acc[16][4];
    #pragma unroll
    for (int nt = 0; nt < 16; nt++)
        #pragma unroll
        for (int j = 0; j < 4; j++) acc[nt][j] = 0.f;

    #pragma unroll
    for (int ks = 0; ks < 8; ks++) {
        const int kp = ks * 8;
        uint32_t ah0 = AH[(wrow + g)     * WSTR + kp + t];
        uint32_t ah1 = AH[(wrow + g + 8) * WSTR + kp + t];
        uint32_t ah2 = AH[(wrow + g)     * WSTR + kp + t + 4];
        uint32_t ah3 = AH[(wrow + g + 8) * WSTR + kp + t + 4];
        uint32_t al0 = AL[(wrow + g)     * WSTR + kp + t];
        uint32_t al1 = AL[(wrow + g + 8) * WSTR + kp + t];
        uint32_t al2 = AL[(wrow + g)     * WSTR + kp + t + 4];
        uint32_t al3 = AL[(wrow + g + 8) * WSTR + kp + t + 4];
        #pragma unroll
        for (int nt = 0; nt < 16; nt++) {
            int n = nt * 8 + g;
            uint32_t bh0 = WH[n * WSTR + kp + t];
            uint32_t bh1 = WH[n * WSTR + kp + t + 4];
            uint32_t bl0 = WL[n * WSTR + kp + t];
            uint32_t bl1 = WL[n * WSTR + kp + t + 4];
            MMA3(acc[nt], ah0, ah1, ah2, ah3, bh0, bh1);
            MMA3(acc[nt], ah0, ah1, ah2, ah3, bl0, bl1);
            MMA3(acc[nt], al0, al1, al2, al3, bh0, bh1);
        }
    }

    // epilogue: H16[row] packed half2
    const int r0 = brow + wrow + g;
    const int r1 = r0 + 8;
    #pragma unroll
    for (int nt = 0; nt < 16; nt++) {
        int wcol = nt * 4 + t;            // half2 word index (cols nt*8+2t, +1)
        if (r0 < N) {
            __half2 h = __floats2half2_rn(acc[nt][0], acc[nt][1]);
            g_H16[(size_t)r0 * 64 + wcol] = *reinterpret_cast<uint32_t*>(&h);
        }
        if (r1 < N) {
            __half2 h = __floats2half2_rn(acc[nt][2], acc[nt][3]);
            g_H16[(size_t)r1 * 64 + wcol] = *reinterpret_cast<uint32_t*>(&h);
        }
    }
}

// ---------------- CSR gather aggregation (fp16 gathers) ----------------
__device__ __forceinline__ float4 ld_h16(int row, int lane) {
    uint2 v = ((const uint2*)(g_H16 + (size_t)row * 64))[lane];
    float2 a = __half22float2(*reinterpret_cast<__half2*>(&v.x));
    float2 b = __half22float2(*reinterpret_cast<__half2*>(&v.y));
    return make_float4(a.x, a.y, b.x, b.y);
}

__global__ __launch_bounds__(256) void k_agg(
    float* __restrict__ O, const float* __restrict__ bias, int N)
{
    int node = (blockIdx.x * blockDim.x + threadIdx.x) >> 5;
    int lane = threadIdx.x & 31;
    if (node >= N) return;

    float di = g_dinv[node];
    float w  = di * di;
    float4 h = ld_h16(node, lane);
    float4 acc;
    acc.x = h.x * w; acc.y = h.y * w; acc.z = h.z * w; acc.w = h.w * w;

    const int start = g_rowstart[node];
    const int cnt   = g_deg[node];
    const int* __restrict__ cs = g_csrc + start;

    int j = 0;
    for (; j + 2 <= cnt; j += 2) {
        int s0 = cs[j];
        int s1 = cs[j + 1];
        float n0 = g_dinv[s0] * di;
        float n1 = g_dinv[s1] * di;
        float4 v0 = ld_h16(s0, lane);
        float4 v1 = ld_h16(s1, lane);
        acc.x = fmaf(v0.x, n0, acc.x); acc.y = fmaf(v0.y, n0, acc.y);
        acc.z = fmaf(v0.z, n0, acc.z); acc.w = fmaf(v0.w, n0, acc.w);
        acc.x = fmaf(v1.x, n1, acc.x); acc.y = fmaf(v1.y, n1, acc.y);
        acc.z = fmaf(v1.z, n1, acc.z); acc.w = fmaf(v1.w, n1, acc.w);
    }
    if (j < cnt) {
        int s0 = cs[j];
        float n0 = g_dinv[s0] * di;
        float4 v0 = ld_h16(s0, lane);
        acc.x = fmaf(v0.x, n0, acc.x); acc.y = fmaf(v0.y, n0, acc.y);
        acc.z = fmaf(v0.z, n0, acc.z); acc.w = fmaf(v0.w, n0, acc.w);
    }

    float4 bb = ((const float4*)bias)[lane];
    acc.x += bb.x; acc.y += bb.y; acc.z += bb.z; acc.w += bb.w;
    ((float4*)(O + (size_t)node * D128))[lane] = acc;
}

// ---------------- BatchNorm stats ----------------
__global__ __launch_bounds__(256) void k_bnreduce(const float* __restrict__ Hx, int N) {
    int f    = threadIdx.x & 127;
    int half = threadIdx.x >> 7;
    float s = 0.f, s2 = 0.f;
    for (int row = blockIdx.x * 2 + half; row < N; row += gridDim.x * 2) {
        float v = Hx[(size_t)row * D128 + f];
        s += v;
        s2 = fmaf(v, v, s2);
    }
    __shared__ float sh[256], sh2[256];
    sh[threadIdx.x] = s; sh2[threadIdx.x] = s2;
    __syncthreads();
    if (threadIdx.x < 128) {
        atomicAdd(&g_sum[f],   sh[f] + sh[f + 128]);
        atomicAdd(&g_sumsq[f], sh2[f] + sh2[f + 128]);
    }
}

// ---------------- launch ----------------
extern "C" void kernel_launch(void* const* d_in, const int* in_sizes, int n_in,
                              void* d_out, int out_size)
{
    const float* x     = (const float*)d_in[0];
    const int*   eidx  = (const int*)d_in[1];
    const float* W1    = (const float*)d_in[2];
    const float* b1    = (const float*)d_in[3];
    const float* gamma = (const float*)d_in[4];
    const float* beta  = (const float*)d_in[5];
    const float* W2    = (const float*)d_in[6];
    const float* b2    = (const float*)d_in[7];
    float*       out   = (float*)d_out;

    const int N = in_sizes[0] / D128;          // 50000
    const int E = in_sizes[1] / 2;             // 800000
    const int* src = eidx;
    const int* dst = eidx + E;

    float* O1; cudaGetSymbolAddress((void**)&O1, g_O1);

    const int GEMM_SMEM = (384 * WSTR + 256) * 4;   // 105472 B
    cudaFuncSetAttribute(k_gemm_tc, cudaFuncAttributeMaxDynamicSharedMemorySize, GEMM_SMEM);

    const int TPB = 256;
    int gridN  = (N + TPB - 1) / TPB;
    int gridE4 = ((E + 3) / 4 + TPB - 1) / TPB;
    int gridG  = (N + 63) / 64;
    int gridA  = (N * 32 + TPB - 1) / TPB;     // warp per node
    int nscan  = (N + SCAN_TPB - 1) / SCAN_TPB;

    // graph structure (per call, deterministic)
    k_setup<<<gridN, TPB>>>(N, W1, W2);
    k_deg<<<gridE4, TPB>>>(dst, E);
    k_scan1<<<nscan, SCAN_TPB>>>(N);
    k_scan3<<<nscan, SCAN_TPB>>>(N);
    k_fill<<<gridE4, TPB>>>(src, dst, E);

    // layer 1
    k_gemm_tc<<<gridG, 128, GEMM_SMEM>>>(x, N, 0, nullptr, nullptr);
    k_agg<<<gridA, TPB>>>(O1, b1, N);

    // batchnorm stats
    k_bnreduce<<<256, TPB>>>(O1, N);

    // layer 2 (BN coef derived in-kernel; BN+ReLU fused into A load)
    k_gemm_tc<<<gridG, 128, GEMM_SMEM>>>(O1, N, 1, gamma, beta);
    k_agg<<<gridA, TPB>>>(out, b2, N);
}